// round 8
// baseline (speedup 1.0000x reference)
#include <cuda_runtime.h>
#include <cuda_fp16.h>
#include <cstdint>

#define N_FEAT 32
#define N_COLS 128          // 4 relations * 32 output features
#define MAX_NODES 524288
#define MAX_EDGES 4194304
#define TN 128              // nodes per transform block

#define XH_STRIDE 40        // halfs per x-tile row (padded, conflict-free ldmatrix)
#define WH_STRIDE 136       // halfs per W row (padded)
#define ST_STRIDE 136       // halfs per staging row

// Scratch: xt fp16 (128 MB), agg fp32 (64 MB x2), CSR arrays.
__device__ __half g_xt[(size_t)MAX_NODES * N_COLS];
__device__ float  g_agg1[(size_t)MAX_NODES * N_FEAT];
__device__ float  g_agg2[(size_t)MAX_NODES * N_FEAT];
__device__ unsigned int g_perm[MAX_EDGES];      // (src<<2)|rel, dst-sorted
__device__ int g_rp[MAX_NODES];                 // local (per-1024-block) excl scan
__device__ int g_cnt[MAX_NODES];                // counts, then local cursor
__device__ int g_bsum[512];                     // block offsets (excl scan of sums)

// ---------------------------------------------------------------------------
// hist: counts per dst.
// ---------------------------------------------------------------------------
__global__ void hist_k(const int* __restrict__ dst, int* __restrict__ cnt, int ne)
{
    const int e = blockIdx.x * blockDim.x + threadIdx.x;
    if (e < ne) atomicAdd(&cnt[__ldg(dst + e)], 1);
}

// 512 blocks x 1024 elements. LOCAL exclusive scan per block; writes rp and
// cursor copies; block totals to bsum.
__global__ void __launch_bounds__(256) scan1_k(
    const int* __restrict__ cnt, int* __restrict__ rp,
    int* __restrict__ cursor, int* __restrict__ bsum)
{
    __shared__ int s[256];
    const int tid = threadIdx.x;
    const int idx = blockIdx.x * 1024 + tid * 4;

    const int4 c = *reinterpret_cast<const int4*>(cnt + idx);
    const int tsum = c.x + c.y + c.z + c.w;

    s[tid] = tsum;
    __syncthreads();
    #pragma unroll
    for (int off = 1; off < 256; off <<= 1) {
        const int v = (tid >= off) ? s[tid - off] : 0;
        __syncthreads();
        s[tid] += v;
        __syncthreads();
    }
    const int excl = s[tid] - tsum;

    int4 o;
    o.x = excl;
    o.y = o.x + c.x;
    o.z = o.y + c.y;
    o.w = o.z + c.z;
    *reinterpret_cast<int4*>(rp + idx)     = o;
    *reinterpret_cast<int4*>(cursor + idx) = o;

    if (tid == 255) bsum[blockIdx.x] = s[255];
}

// Single block: exclusive scan of 512 block sums in place.
__global__ void __launch_bounds__(512) scan2_k(int* __restrict__ bsum)
{
    __shared__ int s[512];
    const int tid = threadIdx.x;
    const int v0 = bsum[tid];
    s[tid] = v0;
    __syncthreads();
    #pragma unroll
    for (int off = 1; off < 512; off <<= 1) {
        const int v = (tid >= off) ? s[tid - off] : 0;
        __syncthreads();
        s[tid] += v;
        __syncthreads();
    }
    bsum[tid] = s[tid] - v0;   // exclusive
}

// Reorder: cursor holds LOCAL offsets; add bsum at write time.
__global__ void reorder_k(
    const int* __restrict__ src, const int* __restrict__ dst,
    const int* __restrict__ et, int* __restrict__ cursor,
    const int* __restrict__ bsum, unsigned int* __restrict__ perm, int ne)
{
    const int e = blockIdx.x * blockDim.x + threadIdx.x;
    if (e >= ne) return;
    const int d = __ldg(dst + e);
    const unsigned int p = ((unsigned int)__ldg(src + e) << 2) | (unsigned int)__ldg(et + e);
    const int pos = atomicAdd(&cursor[d], 1) + __ldg(bsum + (d >> 10));
    perm[pos] = p;
}

// ---------------------------------------------------------------------------
// Aggregation: one warp per TWO nodes, lane = feature. Coalesced perm loads
// over the warp's contiguous edge range; up to 32 gathers in flight; 1-bit
// segmented accumulate (idx >= r1 selects node 1). No atomics.
// rowptr[i] = rp[i] + bsum[i>>10] (scan3 folded in); rowptr[nnodes] = ne.
// ---------------------------------------------------------------------------
__global__ void __launch_bounds__(256) agg_k(
    const __half* __restrict__ xt, const unsigned int* __restrict__ perm,
    const int* __restrict__ rp, const int* __restrict__ bsum,
    float* __restrict__ agg, int nnodes, int ne)
{
    const int wid  = (blockIdx.x * blockDim.x + threadIdx.x) >> 5;
    const int lane = threadIdx.x & 31;
    const int nb   = wid * 2;
    if (nb >= nnodes) return;

    int r = ne;
    if (lane < 3) {
        const int idx = nb + lane;
        if (idx < nnodes)
            r = __ldg(rp + idx) + __ldg(bsum + (idx >> 10));
    }
    const int e0 = __shfl_sync(0xffffffffu, r, 0);
    const int r1 = __shfl_sync(0xffffffffu, r, 1);
    const int e1 = __shfl_sync(0xffffffffu, r, 2);

    float acc0 = 0.f, acc1 = 0.f;
    for (int eb = e0; eb < e1; eb += 32) {
        const int cnt = min(32, e1 - eb);
        const unsigned int pl = (lane < cnt) ? __ldg(perm + eb + lane) : 0u;
        #pragma unroll
        for (int j = 0; j < 32; j++) {
            if (j < cnt) {   // cnt is warp-uniform
                const unsigned int p = __shfl_sync(0xffffffffu, pl, j);
                const float v = __half2float(__ldg(xt + ((size_t)p << 5) + lane));
                if (eb + j < r1) acc0 += v; else acc1 += v;
            }
        }
    }

    agg[(size_t)nb * N_FEAT + lane] = acc0;
    if (nb + 1 < nnodes)
        agg[(size_t)(nb + 1) * N_FEAT + lane] = acc1;
}

// ---------------------------------------------------------------------------
// Tensor-core transform. ZERO_CNT (layer 1 only): piggyback cnt[] zeroing.
// PRE_ACT: in is fp32 agg, apply relu(v + b[d]). Else: in is fp32 x.
// ---------------------------------------------------------------------------
template<bool PRE_ACT>
__global__ void __launch_bounds__(256) transform_k(
    const float* __restrict__ xin, const float* __restrict__ W,
    const float* __restrict__ b, __half* __restrict__ xt,
    int* __restrict__ cnt_zero)
{
    __shared__ __align__(16) unsigned char sm[TN * ST_STRIDE * 2]; // 34816 B
    __half* xh    = reinterpret_cast<__half*>(sm);           // [128][XH_STRIDE]
    __half* wh    = reinterpret_cast<__half*>(sm + 10240);   // [32][WH_STRIDE]
    __half* stage = reinterpret_cast<__half*>(sm);           // [128][ST_STRIDE]

    const int tid  = threadIdx.x;
    const int base = blockIdx.x * TN;

    if (!PRE_ACT) {
        // threads = 2*nnodes; first nnodes zero the count array.
        const int gtid = blockIdx.x * 256 + tid;
        const int nn = (int)gridDim.x << 7;   // gridDim.x * TN
        if (gtid < nn) cnt_zero[gtid] = 0;
    }

    // Fill W smem: wh[d][r*32+o] = half(W[r][d][o]).
    for (int f = tid; f < 1024; f += 256) {
        const float4 v = reinterpret_cast<const float4*>(W)[f];
        const int r = f >> 8, d = (f >> 3) & 31, o4 = f & 7;
        __half* p = &wh[d * WH_STRIDE + r * 32 + o4 * 4];
        p[0] = __float2half_rn(v.x); p[1] = __float2half_rn(v.y);
        p[2] = __float2half_rn(v.z); p[3] = __float2half_rn(v.w);
    }

    // Fill x tile (fp32 in, fp16 out; bias+relu for layer-2 input).
    const float4* xin4 = reinterpret_cast<const float4*>(xin + (size_t)base * N_FEAT);
    for (int f = tid; f < TN * 8; f += 256) {
        float4 v = xin4[f];
        const int i = f >> 3, kq = f & 7;
        if (PRE_ACT) {
            v.x = fmaxf(v.x + __ldg(b + kq * 4 + 0), 0.f);
            v.y = fmaxf(v.y + __ldg(b + kq * 4 + 1), 0.f);
            v.z = fmaxf(v.z + __ldg(b + kq * 4 + 2), 0.f);
            v.w = fmaxf(v.w + __ldg(b + kq * 4 + 3), 0.f);
        }
        __half* d = &xh[i * XH_STRIDE + kq * 4];
        *reinterpret_cast<__half2*>(d)     = __floats2half2_rn(v.x, v.y);
        *reinterpret_cast<__half2*>(d + 2) = __floats2half2_rn(v.z, v.w);
    }
    __syncthreads();

    const int w    = tid >> 5;
    const int lane = tid & 31;
    const int m0   = w * 16;

    uint32_t a[2][4];
    #pragma unroll
    for (int s = 0; s < 2; s++) {
        const int row = m0 + (lane & 15);
        const int col = s * 16 + ((lane >> 4) << 3);
        const uint32_t addr =
            (uint32_t)__cvta_generic_to_shared(&xh[row * XH_STRIDE + col]);
        asm volatile("ldmatrix.sync.aligned.m8n8.x4.shared.b16 {%0,%1,%2,%3}, [%4];"
                     : "=r"(a[s][0]), "=r"(a[s][1]), "=r"(a[s][2]), "=r"(a[s][3])
                     : "r"(addr));
    }

    float acc[16][4];
    #pragma unroll
    for (int j = 0; j < 16; j++)
        #pragma unroll
        for (int q = 0; q < 4; q++) acc[j][q] = 0.f;

    #pragma unroll
    for (int j = 0; j < 16; j++) {
        #pragma unroll
        for (int s = 0; s < 2; s++) {
            const int krow = s * 16 + (lane & 15);
            const uint32_t baddr =
                (uint32_t)__cvta_generic_to_shared(&wh[krow * WH_STRIDE + j * 8]);
            uint32_t b0, b1;
            asm volatile("ldmatrix.sync.aligned.m8n8.x2.trans.shared.b16 {%0,%1}, [%2];"
                         : "=r"(b0), "=r"(b1) : "r"(baddr));
            asm volatile(
                "mma.sync.aligned.m16n8k16.row.col.f32.f16.f16.f32 "
                "{%0,%1,%2,%3}, {%4,%5,%6,%7}, {%8,%9}, {%0,%1,%2,%3};"
                : "+f"(acc[j][0]), "+f"(acc[j][1]), "+f"(acc[j][2]), "+f"(acc[j][3])
                : "r"(a[s][0]), "r"(a[s][1]), "r"(a[s][2]), "r"(a[s][3]),
                  "r"(b0), "r"(b1));
        }
    }
    __syncthreads();   // xh/wh dead; reuse as staging

    const int g  = lane >> 2;
    const int t4 = lane & 3;
    #pragma unroll
    for (int j = 0; j < 16; j++) {
        *reinterpret_cast<__half2*>(&stage[(m0 + g) * ST_STRIDE + j * 8 + t4 * 2]) =
            __floats2half2_rn(acc[j][0], acc[j][1]);
        *reinterpret_cast<__half2*>(&stage[(m0 + g + 8) * ST_STRIDE + j * 8 + t4 * 2]) =
            __floats2half2_rn(acc[j][2], acc[j][3]);
    }
    __syncthreads();

    for (int f = tid; f < TN * 16; f += 256) {
        const int row = f >> 4, ch = f & 15;
        const uint4 v = *reinterpret_cast<const uint4*>(&stage[row * ST_STRIDE + ch * 8]);
        *reinterpret_cast<uint4*>(xt + (size_t)(base + row) * N_COLS + ch * 8) = v;
    }
}

// ---------------------------------------------------------------------------
// Pool: out[g][c] = mean_{i<32} relu(agg2[g*32+i][c] + b[c]).
// ---------------------------------------------------------------------------
__global__ void __launch_bounds__(256) pool_k(
    const float* __restrict__ agg, const float* __restrict__ b,
    float* __restrict__ out, int nnodes)
{
    const int t = blockIdx.x * blockDim.x + threadIdx.x;
    if (t >= nnodes) return;
    const int c = t & 31;
    const int g = t >> 5;
    const float bc = __ldg(b + c);
    const float* p = agg + (size_t)g * 32 * N_FEAT + c;
    float s = 0.f;
    #pragma unroll
    for (int i = 0; i < 32; i++)
        s += fmaxf(p[i * N_FEAT] + bc, 0.f);
    out[t] = s * (1.0f / 32.0f);
}

// ---------------------------------------------------------------------------
// Launch order chosen so ncu (-s 5 -c 1) captures agg_k (launch index 5):
// 0 transform<false>(+cnt zero), 1 hist, 2 scan1, 3 scan2, 4 reorder,
// 5 agg(L1), 6 transform<true>, 7 agg(L2), 8 pool.
// ---------------------------------------------------------------------------
extern "C" void kernel_launch(void* const* d_in, const int* in_sizes, int n_in,
                              void* d_out, int out_size)
{
    const float* x   = (const float*)d_in[0];
    const int*   src = (const int*)  d_in[1];
    const int*   dst = (const int*)  d_in[2];
    const int*   et  = (const int*)  d_in[3];
    const float* W   = (const float*)d_in[4];
    const float* b   = (const float*)d_in[5];

    const int nnodes = in_sizes[0] / N_FEAT;
    const int nedges = in_sizes[1];

    __half *xt; float *agg1, *agg2;
    unsigned int *perm; int *rp, *cnt, *bsum;
    cudaGetSymbolAddress((void**)&xt,   g_xt);
    cudaGetSymbolAddress((void**)&agg1, g_agg1);
    cudaGetSymbolAddress((void**)&agg2, g_agg2);
    cudaGetSymbolAddress((void**)&perm, g_perm);
    cudaGetSymbolAddress((void**)&rp,   g_rp);
    cudaGetSymbolAddress((void**)&cnt,  g_cnt);
    cudaGetSymbolAddress((void**)&bsum, g_bsum);

    const int tf_blocks = nnodes / TN;
    const int eb_blocks = (nedges + 255) / 256;
    const int scan_blks = nnodes / 1024;                    // 512
    const int ag_blocks = ((nnodes / 2) * 32 + 255) / 256;  // warp per 2 nodes

    // 0: Layer-1 transform (independent of CSR) + cnt zeroing piggyback
    transform_k<false><<<tf_blocks, 256>>>(x, W, b, xt, cnt);
    // 1-4: CSR build (scan3 folded into consumers)
    hist_k<<<eb_blocks, 256>>>(dst, cnt, nedges);
    scan1_k<<<scan_blks, 256>>>(cnt, rp, cnt, bsum);   // cnt becomes cursor
    scan2_k<<<1, 512>>>(bsum);
    reorder_k<<<eb_blocks, 256>>>(src, dst, et, cnt, bsum, perm, nedges);
    // 5: Layer-1 aggregation  (ncu captures this one)
    agg_k<<<ag_blocks, 256>>>(xt, perm, rp, bsum, agg1, nnodes, nedges);
    // 6-7: Layer 2
    transform_k<true><<<tf_blocks, 256>>>(agg1, W, b, xt, nullptr);
    agg_k<<<ag_blocks, 256>>>(xt, perm, rp, bsum, agg2, nnodes, nedges);
    // 8: Pool
    pool_k<<<(nnodes + 255) / 256, 256>>>(agg2, b, (float*)d_out, nnodes);
    (void)n_in; (void)out_size;
}

// round 9
// speedup vs baseline: 1.9590x; 1.9590x over previous
#include <cuda_runtime.h>
#include <cuda_fp16.h>
#include <cstdint>

#define N_FEAT 32
#define N_COLS 128          // 4 relations * 32 output features
#define MAX_NODES 524288
#define TN 128              // nodes per transform block

#define XH_STRIDE 40        // halfs per x-tile row (padded, conflict-free ldmatrix)
#define WH_STRIDE 136       // halfs per W row (padded)
#define ST_STRIDE 136       // halfs per staging row

// Scratch: xt fp16 (128 MB), agg buffers fp16 (32 MB each).
__device__ __half g_xt[(size_t)MAX_NODES * N_COLS];
__device__ __half g_agg1[(size_t)MAX_NODES * N_FEAT];
__device__ __half g_agg2[(size_t)MAX_NODES * N_FEAT];

// ---------------------------------------------------------------------------
// Tensor-core transform: xt[n][r*32+o] = sum_d act(in[n][d]) * W[r][d][o]
// (identical to the R4 kernel measured at 43.4us)
// PRE_ACT: in is fp16 agg, apply relu(v + b[d]). Else: in is fp32 x.
// ---------------------------------------------------------------------------
template<bool PRE_ACT>
__global__ void __launch_bounds__(256) transform_k(
    const void* __restrict__ xin_, const float* __restrict__ W,
    const float* __restrict__ b, __half* __restrict__ xt)
{
    __shared__ __align__(16) unsigned char sm[TN * ST_STRIDE * 2]; // 34816 B
    __half* xh    = reinterpret_cast<__half*>(sm);           // [128][XH_STRIDE]
    __half* wh    = reinterpret_cast<__half*>(sm + 10240);   // [32][WH_STRIDE]
    __half* stage = reinterpret_cast<__half*>(sm);           // [128][ST_STRIDE]

    const int tid  = threadIdx.x;
    const int base = blockIdx.x * TN;

    // ---- Fill W smem: wh[d][r*32+o] = half(W[r][d][o]) ----
    for (int f = tid; f < 1024; f += 256) {
        const float4 v = reinterpret_cast<const float4*>(W)[f];
        const int r = f >> 8, d = (f >> 3) & 31, o4 = f & 7;
        __half* p = &wh[d * WH_STRIDE + r * 32 + o4 * 4];
        p[0] = __float2half_rn(v.x); p[1] = __float2half_rn(v.y);
        p[2] = __float2half_rn(v.z); p[3] = __float2half_rn(v.w);
    }

    // ---- Fill x tile (convert to fp16; bias+relu for layer-2 input) ----
    if (PRE_ACT) {
        const __half* xin = reinterpret_cast<const __half*>(xin_);
        for (int f = tid; f < TN * 4; f += 256) {       // 8 halfs per iter
            const int i = f >> 2, kq = f & 3;
            const uint4 pk = *reinterpret_cast<const uint4*>(
                xin + (size_t)(base + i) * N_FEAT + kq * 8);
            const __half2* hp = reinterpret_cast<const __half2*>(&pk);
            const float4 b0 = __ldg(reinterpret_cast<const float4*>(b + kq * 8));
            const float4 b1 = __ldg(reinterpret_cast<const float4*>(b + kq * 8 + 4));
            const float bb[8] = {b0.x, b0.y, b0.z, b0.w, b1.x, b1.y, b1.z, b1.w};
            __half* d = &xh[i * XH_STRIDE + kq * 8];
            #pragma unroll
            for (int j = 0; j < 4; j++) {
                float2 fv = __half22float2(hp[j]);
                fv.x = fmaxf(fv.x + bb[j * 2 + 0], 0.f);
                fv.y = fmaxf(fv.y + bb[j * 2 + 1], 0.f);
                *reinterpret_cast<__half2*>(d + j * 2) = __floats2half2_rn(fv.x, fv.y);
            }
        }
    } else {
        const float4* xin4 = reinterpret_cast<const float4*>(
            reinterpret_cast<const float*>(xin_) + (size_t)base * N_FEAT);
        for (int f = tid; f < TN * 8; f += 256) {       // 4 floats per iter
            const float4 v = xin4[f];
            const int i = f >> 3, kq = f & 7;
            __half* d = &xh[i * XH_STRIDE + kq * 4];
            *reinterpret_cast<__half2*>(d)     = __floats2half2_rn(v.x, v.y);
            *reinterpret_cast<__half2*>(d + 2) = __floats2half2_rn(v.z, v.w);
        }
    }
    __syncthreads();

    // ---- MMA ----
    const int w    = tid >> 5;
    const int lane = tid & 31;
    const int m0   = w * 16;

    uint32_t a[2][4];
    #pragma unroll
    for (int s = 0; s < 2; s++) {
        const int row = m0 + (lane & 15);
        const int col = s * 16 + ((lane >> 4) << 3);
        const uint32_t addr =
            (uint32_t)__cvta_generic_to_shared(&xh[row * XH_STRIDE + col]);
        asm volatile("ldmatrix.sync.aligned.m8n8.x4.shared.b16 {%0,%1,%2,%3}, [%4];"
                     : "=r"(a[s][0]), "=r"(a[s][1]), "=r"(a[s][2]), "=r"(a[s][3])
                     : "r"(addr));
    }

    float acc[16][4];
    #pragma unroll
    for (int j = 0; j < 16; j++)
        #pragma unroll
        for (int q = 0; q < 4; q++) acc[j][q] = 0.f;

    #pragma unroll
    for (int j = 0; j < 16; j++) {
        #pragma unroll
        for (int s = 0; s < 2; s++) {
            const int krow = s * 16 + (lane & 15);
            const uint32_t baddr =
                (uint32_t)__cvta_generic_to_shared(&wh[krow * WH_STRIDE + j * 8]);
            uint32_t b0, b1;
            asm volatile("ldmatrix.sync.aligned.m8n8.x2.trans.shared.b16 {%0,%1}, [%2];"
                         : "=r"(b0), "=r"(b1) : "r"(baddr));
            asm volatile(
                "mma.sync.aligned.m16n8k16.row.col.f32.f16.f16.f32 "
                "{%0,%1,%2,%3}, {%4,%5,%6,%7}, {%8,%9}, {%0,%1,%2,%3};"
                : "+f"(acc[j][0]), "+f"(acc[j][1]), "+f"(acc[j][2]), "+f"(acc[j][3])
                : "r"(a[s][0]), "r"(a[s][1]), "r"(a[s][2]), "r"(a[s][3]),
                  "r"(b0), "r"(b1));
        }
    }
    __syncthreads();   // xh/wh dead; reuse as staging

    // ---- Stage fragments ----
    const int g  = lane >> 2;
    const int t4 = lane & 3;
    #pragma unroll
    for (int j = 0; j < 16; j++) {
        *reinterpret_cast<__half2*>(&stage[(m0 + g) * ST_STRIDE + j * 8 + t4 * 2]) =
            __floats2half2_rn(acc[j][0], acc[j][1]);
        *reinterpret_cast<__half2*>(&stage[(m0 + g + 8) * ST_STRIDE + j * 8 + t4 * 2]) =
            __floats2half2_rn(acc[j][2], acc[j][3]);
    }
    __syncthreads();

    // ---- Coalesced store: 128 rows x 16 uint4 ----
    for (int f = tid; f < TN * 16; f += 256) {
        const int row = f >> 4, ch = f & 15;
        const uint4 v = *reinterpret_cast<const uint4*>(&stage[row * ST_STRIDE + ch * 8]);
        *reinterpret_cast<uint4*>(xt + (size_t)(base + row) * N_COLS + ch * 8) = v;
    }
}

// ---------------------------------------------------------------------------
// Zero fill (n4 float4 elements).
// ---------------------------------------------------------------------------
__global__ void zero_k(float4* __restrict__ p, int n4)
{
    const int i = blockIdx.x * blockDim.x + threadIdx.x;
    if (i < n4) p[i] = make_float4(0.f, 0.f, 0.f, 0.f);
}

// ---------------------------------------------------------------------------
// Edge scatter: agg_fp16[dst] += xt_fp16[src, etype*32 : +32].
// 4 lanes/edge: each lane gathers 16B (8 halfs) and issues ONE
// red.add.v4.f16x2. Shallow chain (1 gather -> 1 RED) for latency hiding.
// ---------------------------------------------------------------------------
__global__ void __launch_bounds__(256) scatter_k(
    const __half* __restrict__ xt, const int* __restrict__ src,
    const int* __restrict__ dst, const int* __restrict__ et,
    __half* __restrict__ agg, int nedges)
{
    const int t = blockIdx.x * blockDim.x + threadIdx.x;
    const int e = t >> 2;
    if (e >= nedges) return;
    const int q = t & 3;

    const int s = __ldg(src + e);
    const int d = __ldg(dst + e);
    const int r = __ldg(et  + e);

    const uint4 p = *reinterpret_cast<const uint4*>(
        xt + (size_t)s * N_COLS + r * N_FEAT + q * 8);

    __half* ap = agg + (size_t)d * N_FEAT + q * 8;
    asm volatile("red.global.add.noftz.v4.f16x2 [%0], {%1, %2, %3, %4};"
                 :: "l"(ap), "r"(p.x), "r"(p.y), "r"(p.z), "r"(p.w)
                 : "memory");
}

// ---------------------------------------------------------------------------
// Pool: out[g][c] = mean_{i<32} relu(agg2[g*32+i][c] + b[c]).
// ---------------------------------------------------------------------------
__global__ void __launch_bounds__(256) pool_k(
    const __half* __restrict__ agg, const float* __restrict__ b,
    float* __restrict__ out, int nnodes)
{
    const int t = blockIdx.x * blockDim.x + threadIdx.x;
    if (t >= nnodes) return;
    const int c = t & 31;
    const int g = t >> 5;
    const float bc = __ldg(b + c);
    const __half* p = agg + (size_t)g * 32 * N_FEAT + c;
    float s = 0.f;
    #pragma unroll
    for (int i = 0; i < 32; i++)
        s += fmaxf(__half2float(p[i * N_FEAT]) + bc, 0.f);
    out[t] = s * (1.0f / 32.0f);
}

// ---------------------------------------------------------------------------
// Launch order: 0 zero(agg1), 1 zero(agg2), 2 tf<0>, 3 scatter1 (<- ncu
// captures launch index 3), 4 tf<1>, 5 scatter2, 6 pool.
// ---------------------------------------------------------------------------
extern "C" void kernel_launch(void* const* d_in, const int* in_sizes, int n_in,
                              void* d_out, int out_size)
{
    const float* x   = (const float*)d_in[0];
    const int*   src = (const int*)  d_in[1];
    const int*   dst = (const int*)  d_in[2];
    const int*   et  = (const int*)  d_in[3];
    const float* W   = (const float*)d_in[4];
    const float* b   = (const float*)d_in[5];

    const int nnodes = in_sizes[0] / N_FEAT;
    const int nedges = in_sizes[1];

    __half *xt, *agg1, *agg2;
    cudaGetSymbolAddress((void**)&xt,   g_xt);
    cudaGetSymbolAddress((void**)&agg1, g_agg1);
    cudaGetSymbolAddress((void**)&agg2, g_agg2);

    const int tf_blocks = nnodes / TN;
    const int n4        = nnodes * N_FEAT * (int)sizeof(__half) / 16;
    const int z_blocks  = (n4 + 255) / 256;
    const int sc_blocks = (nedges * 4 + 255) / 256;

    // 0-1: zero both agg buffers up front
    zero_k<<<z_blocks, 256>>>((float4*)agg1, n4);
    zero_k<<<z_blocks, 256>>>((float4*)agg2, n4);

    // 2-3: Layer 1
    transform_k<false><<<tf_blocks, 256>>>(x, W, b, xt);
    scatter_k<<<sc_blocks, 256>>>(xt, src, dst, et, agg1, nedges);

    // 4-5: Layer 2 (input = relu(agg1 + b), fused into transform)
    transform_k<true><<<tf_blocks, 256>>>(agg1, W, b, xt);
    scatter_k<<<sc_blocks, 256>>>(xt, src, dst, et, agg2, nedges);

    // 6: Pool (bias+relu fused)
    pool_k<<<(nnodes + 255) / 256, 256>>>(agg2, b, (float*)d_out, nnodes);
    (void)n_in; (void)out_size;
}